// round 14
// baseline (speedup 1.0000x reference)
#include <cuda_runtime.h>
#include <cstdint>

#define FULL_MASK 0xffffffffu
typedef unsigned long long ull;

constexpr int N = 64;
constexpr int WPB = 2;
constexpr int MAX_SWEEPS = 11;
constexpr int STR = 66;   // smem stride in floats (even -> 8B-aligned columns)

__device__ __forceinline__ ull pk2(float a, float b) {
    ull r; asm("mov.b64 %0, {%1,%2};" : "=l"(r) : "f"(a), "f"(b)); return r;
}
__device__ __forceinline__ void upk2(ull v, float& a, float& b) {
    asm("mov.b64 {%0,%1}, %2;" : "=f"(a), "=f"(b) : "l"(v));
}
__device__ __forceinline__ ull fma2(ull a, ull b, ull c) {
    ull r; asm("fma.rn.f32x2 %0,%1,%2,%3;" : "=l"(r) : "l"(a), "l"(b), "l"(c)); return r;
}
__device__ __forceinline__ ull mul2(ull a, ull b) {
    ull r; asm("mul.rn.f32x2 %0,%1,%2;" : "=l"(r) : "l"(a), "l"(b)); return r;
}
__device__ __forceinline__ ull add2(ull a, ull b) {
    ull r; asm("add.rn.f32x2 %0,%1,%2;" : "=l"(r) : "l"(a), "l"(b)); return r;
}
__device__ __forceinline__ float hsum2(ull v) { float a, b; upk2(v, a, b); return a + b; }

// One warp per matrix.  (R7 champion + short scalar chain.)
// 1) Cholesky X = L L^T (smem).
// 2) One-sided Jacobi on columns of L, recursive merge ordering (63 rounds =
//    all 2016 pairs). Deferred-cosine rotations: column stored as sigma * h~;
//    rotation applies only tangent FMAs, cosine folds into sigma (and inverse
//    scale isigma maintained so tangent constants need no divides).
//    Direct tangent: t = 2g*sign(d)/(|d|+sqrt(d^2+4g^2)) -> 2 serial MUFU on
//    the critical path (was 5). Divergent if(rot).
//    Dead levers (measured): predication/fusion (+regs), launch_bounds
//    min-blocks (spills), loose thresholds (stalls), butterfly split (regs or
//    local-mem demotion).
// 3) lambda_k = ||h_k||^2 ; Y = sum_k (log l_k / l_k) h_k h_k^T.
__global__ void __launch_bounds__(WPB * 32)
logeig_kernel(const float* __restrict__ X, float* __restrict__ Y, int nmat)
{
    __shared__ float S[WPB][N * STR + N];

    const int warp = threadIdx.x >> 5;
    const int lane = threadIdx.x & 31;
    const int mat  = blockIdx.x * WPB + warp;
    if (mat >= nmat) return;

    float* C  = &S[warp][0];
    float* wv = C + N * STR;

    const float* Xm = X + (size_t)mat * N * N;

    // ---- Load X (coalesced) ----
#pragma unroll
    for (int i = 0; i < N; i++) {
        float2 v = *reinterpret_cast<const float2*>(Xm + i * N + 2 * lane);
        C[i * STR + 2 * lane]     = v.x;
        C[i * STR + 2 * lane + 1] = v.y;
    }
    __syncwarp();

    // ---- Cholesky (lower), in place ----
#pragma unroll 1
    for (int k = 0; k < N; k++) {
        float d    = sqrtf(C[k * STR + k]);
        float dinv = 1.0f / d;
        for (int i = k + 1 + lane; i < N; i += 32)
            C[i * STR + k] *= dinv;
        if (lane == 0) C[k * STR + k] = d;
        __syncwarp();
        for (int j = k + 1 + lane; j < N; j += 32) {
            float ljk = C[j * STR + k];
#pragma unroll 4
            for (int i = j; i < N; i++)
                C[i * STR + j] = fmaf(-C[i * STR + k], ljk, C[i * STR + j]);
        }
        __syncwarp();
    }

    // ---- Extract columns 2*lane, 2*lane+1 of L into packed registers ----
    ull x[32], y[32];
    {
        const int c0 = 2 * lane, c1 = 2 * lane + 1;
#pragma unroll
        for (int j = 0; j < 32; j++) {
            int i0 = 2 * j, i1 = 2 * j + 1;
            float a0 = (i0 >= c0) ? C[i0 * STR + c0] : 0.f;
            float a1 = (i1 >= c0) ? C[i1 * STR + c0] : 0.f;
            float b0 = (i0 >= c1) ? C[i0 * STR + c1] : 0.f;
            float b1 = (i1 >= c1) ? C[i1 * STR + c1] : 0.f;
            x[j] = pk2(a0, a1);
            y[j] = pk2(b0, b1);
        }
    }
    __syncwarp();

    float na, nb;                       // true squared norms
    float sx = 1.f, sy = 1.f;           // deferred scales (true col = s * stored)
    float isx = 1.f, isy = 1.f;         // maintained inverses of the scales

    // ---- Jacobi sweeps ----
#pragma unroll 1
    for (int sweep = 0; sweep < MAX_SWEEPS; sweep++) {
        // Fold scales back into columns (skip on sweep 0); exact norm refresh.
        {
            if (sweep) {
                ull sx2 = pk2(sx, sx), sy2 = pk2(sy, sy);
#pragma unroll
                for (int j = 0; j < 32; j++) {
                    x[j] = mul2(sx2, x[j]);
                    y[j] = mul2(sy2, y[j]);
                }
                sx = 1.f; sy = 1.f; isx = 1.f; isy = 1.f;
            }
            ull a0 = 0, a1 = 0, b0 = 0, b1 = 0;
#pragma unroll
            for (int j = 0; j < 32; j += 2) {
                a0 = fma2(x[j], x[j], a0);     a1 = fma2(x[j + 1], x[j + 1], a1);
                b0 = fma2(y[j], y[j], b0);     b1 = fma2(y[j + 1], y[j + 1], b1);
            }
            na = hsum2(add2(a0, a1));
            nb = hsum2(add2(b0, b1));
        }

        bool any_big = false;
#pragma unroll 1
        for (int k = 0; k < 6; k++) {
            const int g    = 32 >> k;
            const int lin  = lane & (g - 1);
            const int rsrc = (lane & ~(g - 1)) | ((lin + 1) & (g - 1));
#pragma unroll 1
            for (int r = 0; r < g; r++) {
                ull d0 = 0, d1 = 0, d2 = 0, d3 = 0;
#pragma unroll
                for (int j = 0; j < 32; j += 4) {
                    d0 = fma2(x[j],     y[j],     d0);
                    d1 = fma2(x[j + 1], y[j + 1], d1);
                    d2 = fma2(x[j + 2], y[j + 2], d2);
                    d3 = fma2(x[j + 3], y[j + 3], d3);
                }
                float gt = hsum2(add2(add2(d0, d1), add2(d2, d3)));
                float gd = (sx * sy) * gt;   // true dot
                float g2 = gd * gd;

                bool rot = (g2 > 1e-9f * na * nb);
                if (rot) {
                    // t = 2*gd*sign(dlt) / (|dlt| + sqrt(dlt^2 + 4*gd^2))
                    float dlt = nb - na;
                    float rr  = sqrtf(fmaf(dlt, dlt, 4.0f * g2));
                    float t   = __fdividef(2.0f * gd, copysignf(fabsf(dlt) + rr, dlt));
                    any_big |= (t * t > 1e-8f);
                    // tangent constants ready now (no divides):
                    float tx = t * sy * isx;   // x~' = x~ - tx*y~
                    float ty = t * sx * isy;   // y~' = y~ + ty*x~(old)
                    ull mtx2 = pk2(-tx, -tx), ty2 = pk2(ty, ty);
                    // scale updates off the critical path:
                    float h2 = fmaf(t, t, 1.0f);
                    float c  = rsqrtf(h2);
                    float ic = sqrtf(h2);
                    sx *= c;   sy *= c;
                    isx *= ic; isy *= ic;
                    na = fmaf(-t, gd, na);
                    nb = fmaf( t, gd, nb);
#pragma unroll
                    for (int j = 0; j < 32; j++) {
                        ull u = x[j];
                        x[j] = fma2(mtx2, y[j], u);
                        y[j] = fma2(ty2, u, y[j]);
                    }
                }
                if (r != g - 1) {
#pragma unroll
                    for (int j = 0; j < 32; j++)
                        y[j] = __shfl_sync(FULL_MASK, y[j], rsrc);
                    nb  = __shfl_sync(FULL_MASK, nb,  rsrc);
                    sy  = __shfl_sync(FULL_MASK, sy,  rsrc);
                    isy = __shfl_sync(FULL_MASK, isy, rsrc);
                }
            }
            if (g > 1) {
                const int  h    = g >> 1;
                const int  base = lane & ~(g - 1);
                const bool tx_  = (lin < h);
                const int  sA   = base + (tx_ ? 2 * lin : 2 * lin - g);
                const int  sB   = sA + 1;
#pragma unroll
                for (int j = 0; j < 32; j++) {
                    ull ax = __shfl_sync(FULL_MASK, x[j], sA);
                    ull ay = __shfl_sync(FULL_MASK, y[j], sA);
                    ull bx = __shfl_sync(FULL_MASK, x[j], sB);
                    ull by = __shfl_sync(FULL_MASK, y[j], sB);
                    x[j] = tx_ ? ax : ay;
                    y[j] = tx_ ? bx : by;
                }
                float ax = __shfl_sync(FULL_MASK, na, sA);
                float ay = __shfl_sync(FULL_MASK, nb, sA);
                float bx = __shfl_sync(FULL_MASK, na, sB);
                float by = __shfl_sync(FULL_MASK, nb, sB);
                na = tx_ ? ax : ay;
                nb = tx_ ? bx : by;
                float px = __shfl_sync(FULL_MASK, sx, sA);
                float py = __shfl_sync(FULL_MASK, sy, sA);
                float qx = __shfl_sync(FULL_MASK, sx, sB);
                float qy = __shfl_sync(FULL_MASK, sy, sB);
                sx = tx_ ? px : py;
                sy = tx_ ? qx : qy;
                float ux = __shfl_sync(FULL_MASK, isx, sA);
                float uy = __shfl_sync(FULL_MASK, isy, sA);
                float vx = __shfl_sync(FULL_MASK, isx, sB);
                float vy = __shfl_sync(FULL_MASK, isy, sB);
                isx = tx_ ? ux : uy;
                isy = tx_ ? vx : vy;
            }
        }
        if (!__any_sync(FULL_MASK, any_big)) break;
    }

    // ---- Exact eigenvalues + weights (fold sigma^2 into weight) ----
    {
        ull a0 = 0, a1 = 0, b0 = 0, b1 = 0;
#pragma unroll
        for (int j = 0; j < 32; j += 2) {
            a0 = fma2(x[j], x[j], a0);     a1 = fma2(x[j + 1], x[j + 1], a1);
            b0 = fma2(y[j], y[j], b0);     b1 = fma2(y[j + 1], y[j + 1], b1);
        }
        float s2x = hsum2(add2(a0, a1));
        float s2y = hsum2(add2(b0, b1));
        na = (sx * sx) * s2x;               // true lambda
        nb = (sy * sy) * s2y;
        float wx = (sx * sx) * logf(na) / na;
        float wy = (sy * sy) * logf(nb) / nb;

        __syncwarp();
        ull* c0 = reinterpret_cast<ull*>(C + (2 * lane) * STR);
        ull* c1 = reinterpret_cast<ull*>(C + (2 * lane + 1) * STR);
#pragma unroll
        for (int j = 0; j < 32; j++) { c0[j] = x[j]; c1[j] = y[j]; }
        wv[2 * lane]     = wx;
        wv[2 * lane + 1] = wy;
    }
    __syncwarp();

    // ---- Y[i][j] = sum_k w_k H~[i][k] H~[j][k]; lane -> output cols lane, lane+32 ----
    ull accx[32], accy[32];
#pragma unroll
    for (int j = 0; j < 32; j++) { accx[j] = 0; accy[j] = 0; }

    const int j0 = lane, j1 = lane + 32;
#pragma unroll 1
    for (int k = 0; k < N; k++) {
        const float* ck = C + k * STR;
        float w  = wv[k];
        float a0 = w * ck[j0];
        float a1 = w * ck[j1];
        ull a02 = pk2(a0, a0), a12 = pk2(a1, a1);
        const ull* cp = reinterpret_cast<const ull*>(ck);
#pragma unroll
        for (int j = 0; j < 32; j++) {
            ull b = cp[j];                 // broadcast
            accx[j] = fma2(a02, b, accx[j]);
            accy[j] = fma2(a12, b, accy[j]);
        }
    }

    float* Ym = Y + (size_t)mat * N * N;
#pragma unroll
    for (int j = 0; j < 32; j++) {
        float lo, hi;
        upk2(accx[j], lo, hi);
        Ym[(2 * j) * N + j0]     = lo;
        Ym[(2 * j + 1) * N + j0] = hi;
        upk2(accy[j], lo, hi);
        Ym[(2 * j) * N + j1]     = lo;
        Ym[(2 * j + 1) * N + j1] = hi;
    }
}

extern "C" void kernel_launch(void* const* d_in, const int* in_sizes, int n_in,
                              void* d_out, int out_size)
{
    const float* X = (const float*)d_in[0];
    float* Y = (float*)d_out;
    int nmat = in_sizes[0] / (N * N);
    int blocks = (nmat + WPB - 1) / WPB;
    logeig_kernel<<<blocks, WPB * 32>>>(X, Y, nmat);
}

// round 16
// speedup vs baseline: 1.1758x; 1.1758x over previous
#include <cuda_runtime.h>
#include <cstdint>

#define FULL_MASK 0xffffffffu
typedef unsigned long long ull;

constexpr int N = 64;
constexpr int WPB = 2;
constexpr int MAX_SWEEPS = 11;
constexpr int STR = 66;   // smem stride in floats (even -> 8B-aligned columns)

__device__ __forceinline__ ull pk2(float a, float b) {
    ull r; asm("mov.b64 %0, {%1,%2};" : "=l"(r) : "f"(a), "f"(b)); return r;
}
__device__ __forceinline__ void upk2(ull v, float& a, float& b) {
    asm("mov.b64 {%0,%1}, %2;" : "=f"(a), "=f"(b) : "l"(v));
}
__device__ __forceinline__ ull fma2(ull a, ull b, ull c) {
    ull r; asm("fma.rn.f32x2 %0,%1,%2,%3;" : "=l"(r) : "l"(a), "l"(b), "l"(c)); return r;
}
__device__ __forceinline__ ull mul2(ull a, ull b) {
    ull r; asm("mul.rn.f32x2 %0,%1,%2;" : "=l"(r) : "l"(a), "l"(b)); return r;
}
__device__ __forceinline__ ull add2(ull a, ull b) {
    ull r; asm("add.rn.f32x2 %0,%1,%2;" : "=l"(r) : "l"(a), "l"(b)); return r;
}
__device__ __forceinline__ float hsum2(ull v) { float a, b; upk2(v, a, b); return a + b; }

// One warp per matrix.  (R13 champion + branch-local direct tangent.)
// 1) Cholesky X = L L^T (smem).
// 2) One-sided Jacobi on columns of L, recursive merge ordering (63 rounds =
//    all 2016 pairs). Deferred-cosine rotations: column stored as sigma * h~,
//    rotation applies only tangent FMAs, cosine folds into sigma; scales
//    folded back at each sweep-start refresh. Divergent if(rot).
//    Direct tangent t = 2g*sign(d)/(|d|+sqrt(d^2+4g^2)) with INLINE divides
//    for tx,ty (mutually independent): serial MUFU depth 4 -> 3. All
//    temporaries branch-local -- no persistent scalars (R14's isx/isy pushed
//    regs past the 170 cliff: 64K/(regs*64) drops 6 -> 5 blocks).
//    Dead levers (measured): predication/fusion, launch_bounds min-blocks,
//    loose thresholds, butterfly split, persistent inverse scales.
// 3) lambda_k = ||h_k||^2 ; Y = sum_k (log l_k / l_k) h_k h_k^T.
__global__ void __launch_bounds__(WPB * 32)
logeig_kernel(const float* __restrict__ X, float* __restrict__ Y, int nmat)
{
    __shared__ float S[WPB][N * STR + N];

    const int warp = threadIdx.x >> 5;
    const int lane = threadIdx.x & 31;
    const int mat  = blockIdx.x * WPB + warp;
    if (mat >= nmat) return;

    float* C  = &S[warp][0];
    float* wv = C + N * STR;

    const float* Xm = X + (size_t)mat * N * N;

    // ---- Load X (coalesced) ----
#pragma unroll
    for (int i = 0; i < N; i++) {
        float2 v = *reinterpret_cast<const float2*>(Xm + i * N + 2 * lane);
        C[i * STR + 2 * lane]     = v.x;
        C[i * STR + 2 * lane + 1] = v.y;
    }
    __syncwarp();

    // ---- Cholesky (lower), in place ----
#pragma unroll 1
    for (int k = 0; k < N; k++) {
        float d    = sqrtf(C[k * STR + k]);
        float dinv = 1.0f / d;
        for (int i = k + 1 + lane; i < N; i += 32)
            C[i * STR + k] *= dinv;
        if (lane == 0) C[k * STR + k] = d;
        __syncwarp();
        for (int j = k + 1 + lane; j < N; j += 32) {
            float ljk = C[j * STR + k];
#pragma unroll 4
            for (int i = j; i < N; i++)
                C[i * STR + j] = fmaf(-C[i * STR + k], ljk, C[i * STR + j]);
        }
        __syncwarp();
    }

    // ---- Extract columns 2*lane, 2*lane+1 of L into packed registers ----
    ull x[32], y[32];
    {
        const int c0 = 2 * lane, c1 = 2 * lane + 1;
#pragma unroll
        for (int j = 0; j < 32; j++) {
            int i0 = 2 * j, i1 = 2 * j + 1;
            float a0 = (i0 >= c0) ? C[i0 * STR + c0] : 0.f;
            float a1 = (i1 >= c0) ? C[i1 * STR + c0] : 0.f;
            float b0 = (i0 >= c1) ? C[i0 * STR + c1] : 0.f;
            float b1 = (i1 >= c1) ? C[i1 * STR + c1] : 0.f;
            x[j] = pk2(a0, a1);
            y[j] = pk2(b0, b1);
        }
    }
    __syncwarp();

    float na, nb;             // true squared norms
    float sx = 1.f, sy = 1.f; // deferred column scales (true col = s * stored col)

    // ---- Jacobi sweeps ----
#pragma unroll 1
    for (int sweep = 0; sweep < MAX_SWEEPS; sweep++) {
        // Fold scales back into columns (skip on sweep 0); exact norm refresh.
        {
            if (sweep) {
                ull sx2 = pk2(sx, sx), sy2 = pk2(sy, sy);
#pragma unroll
                for (int j = 0; j < 32; j++) {
                    x[j] = mul2(sx2, x[j]);
                    y[j] = mul2(sy2, y[j]);
                }
                sx = 1.f; sy = 1.f;
            }
            ull a0 = 0, a1 = 0, b0 = 0, b1 = 0;
#pragma unroll
            for (int j = 0; j < 32; j += 2) {
                a0 = fma2(x[j], x[j], a0);     a1 = fma2(x[j + 1], x[j + 1], a1);
                b0 = fma2(y[j], y[j], b0);     b1 = fma2(y[j + 1], y[j + 1], b1);
            }
            na = hsum2(add2(a0, a1));
            nb = hsum2(add2(b0, b1));
        }

        bool any_big = false;
#pragma unroll 1
        for (int k = 0; k < 6; k++) {
            const int g    = 32 >> k;
            const int lin  = lane & (g - 1);
            const int rsrc = (lane & ~(g - 1)) | ((lin + 1) & (g - 1));
#pragma unroll 1
            for (int r = 0; r < g; r++) {
                ull d0 = 0, d1 = 0, d2 = 0, d3 = 0;
#pragma unroll
                for (int j = 0; j < 32; j += 4) {
                    d0 = fma2(x[j],     y[j],     d0);
                    d1 = fma2(x[j + 1], y[j + 1], d1);
                    d2 = fma2(x[j + 2], y[j + 2], d2);
                    d3 = fma2(x[j + 3], y[j + 3], d3);
                }
                float gt = hsum2(add2(add2(d0, d1), add2(d2, d3)));
                float gd = (sx * sy) * gt;   // true dot
                float g2 = gd * gd;

                bool rot = (g2 > 1e-9f * na * nb);
                if (rot) {
                    // t = 2*gd*sign(dlt) / (|dlt| + sqrt(dlt^2 + 4*gd^2))
                    float dlt = nb - na;
                    float rr  = sqrtf(fmaf(dlt, dlt, 4.0f * g2));
                    float t   = __fdividef(2.0f * gd, copysignf(fabsf(dlt) + rr, dlt));
                    any_big |= (t * t > 1e-8f);
                    // independent divides (both ready one MUFU after t):
                    float tx = t * __fdividef(sy, sx);   // x~' = x~ - tx*y~
                    float ty = t * __fdividef(sx, sy);   // y~' = y~ + ty*x~(old)
                    ull mtx2 = pk2(-tx, -tx), ty2 = pk2(ty, ty);
                    // off the critical path:
                    float c = rsqrtf(fmaf(t, t, 1.0f));
                    sx *= c; sy *= c;
                    na = fmaf(-t, gd, na);
                    nb = fmaf( t, gd, nb);
#pragma unroll
                    for (int j = 0; j < 32; j++) {
                        ull u = x[j];
                        x[j] = fma2(mtx2, y[j], u);
                        y[j] = fma2(ty2, u, y[j]);
                    }
                }
                if (r != g - 1) {
#pragma unroll
                    for (int j = 0; j < 32; j++)
                        y[j] = __shfl_sync(FULL_MASK, y[j], rsrc);
                    nb = __shfl_sync(FULL_MASK, nb, rsrc);
                    sy = __shfl_sync(FULL_MASK, sy, rsrc);
                }
            }
            if (g > 1) {
                const int  h    = g >> 1;
                const int  base = lane & ~(g - 1);
                const bool tx_  = (lin < h);
                const int  sA   = base + (tx_ ? 2 * lin : 2 * lin - g);
                const int  sB   = sA + 1;
#pragma unroll
                for (int j = 0; j < 32; j++) {
                    ull ax = __shfl_sync(FULL_MASK, x[j], sA);
                    ull ay = __shfl_sync(FULL_MASK, y[j], sA);
                    ull bx = __shfl_sync(FULL_MASK, x[j], sB);
                    ull by = __shfl_sync(FULL_MASK, y[j], sB);
                    x[j] = tx_ ? ax : ay;
                    y[j] = tx_ ? bx : by;
                }
                float ax = __shfl_sync(FULL_MASK, na, sA);
                float ay = __shfl_sync(FULL_MASK, nb, sA);
                float bx = __shfl_sync(FULL_MASK, na, sB);
                float by = __shfl_sync(FULL_MASK, nb, sB);
                na = tx_ ? ax : ay;
                nb = tx_ ? bx : by;
                float px = __shfl_sync(FULL_MASK, sx, sA);
                float py = __shfl_sync(FULL_MASK, sy, sA);
                float qx = __shfl_sync(FULL_MASK, sx, sB);
                float qy = __shfl_sync(FULL_MASK, sy, sB);
                sx = tx_ ? px : py;
                sy = tx_ ? qx : qy;
            }
        }
        if (!__any_sync(FULL_MASK, any_big)) break;
    }

    // ---- Exact eigenvalues + weights (fold sigma^2 into weight) ----
    {
        ull a0 = 0, a1 = 0, b0 = 0, b1 = 0;
#pragma unroll
        for (int j = 0; j < 32; j += 2) {
            a0 = fma2(x[j], x[j], a0);     a1 = fma2(x[j + 1], x[j + 1], a1);
            b0 = fma2(y[j], y[j], b0);     b1 = fma2(y[j + 1], y[j + 1], b1);
        }
        float s2x = hsum2(add2(a0, a1));
        float s2y = hsum2(add2(b0, b1));
        na = (sx * sx) * s2x;               // true lambda
        nb = (sy * sy) * s2y;
        float wx = (sx * sx) * logf(na) / na;
        float wy = (sy * sy) * logf(nb) / nb;

        __syncwarp();
        ull* c0 = reinterpret_cast<ull*>(C + (2 * lane) * STR);
        ull* c1 = reinterpret_cast<ull*>(C + (2 * lane + 1) * STR);
#pragma unroll
        for (int j = 0; j < 32; j++) { c0[j] = x[j]; c1[j] = y[j]; }
        wv[2 * lane]     = wx;
        wv[2 * lane + 1] = wy;
    }
    __syncwarp();

    // ---- Y[i][j] = sum_k w_k H~[i][k] H~[j][k]; lane -> output cols lane, lane+32 ----
    ull accx[32], accy[32];
#pragma unroll
    for (int j = 0; j < 32; j++) { accx[j] = 0; accy[j] = 0; }

    const int j0 = lane, j1 = lane + 32;
#pragma unroll 1
    for (int k = 0; k < N; k++) {
        const float* ck = C + k * STR;
        float w  = wv[k];
        float a0 = w * ck[j0];
        float a1 = w * ck[j1];
        ull a02 = pk2(a0, a0), a12 = pk2(a1, a1);
        const ull* cp = reinterpret_cast<const ull*>(ck);
#pragma unroll
        for (int j = 0; j < 32; j++) {
            ull b = cp[j];                 // broadcast
            accx[j] = fma2(a02, b, accx[j]);
            accy[j] = fma2(a12, b, accy[j]);
        }
    }

    float* Ym = Y + (size_t)mat * N * N;
#pragma unroll
    for (int j = 0; j < 32; j++) {
        float lo, hi;
        upk2(accx[j], lo, hi);
        Ym[(2 * j) * N + j0]     = lo;
        Ym[(2 * j + 1) * N + j0] = hi;
        upk2(accy[j], lo, hi);
        Ym[(2 * j) * N + j1]     = lo;
        Ym[(2 * j + 1) * N + j1] = hi;
    }
}

extern "C" void kernel_launch(void* const* d_in, const int* in_sizes, int n_in,
                              void* d_out, int out_size)
{
    const float* X = (const float*)d_in[0];
    float* Y = (float*)d_out;
    int nmat = in_sizes[0] / (N * N);
    int blocks = (nmat + WPB - 1) / WPB;
    logeig_kernel<<<blocks, WPB * 32>>>(X, Y, nmat);
}